// round 2
// baseline (speedup 1.0000x reference)
#include <cuda_runtime.h>
#include <math.h>

#define BB 64
#define SS 512
#define II 512
#define HH 1024
#define KK0 1536
#define KK1 2048
#define NCTA 148
#define NTHR 256
#define KC 128

// Persistent device state (allowed: __device__ globals, no allocation)
__device__ float g_h0[2][BB * HH];
__device__ float g_h1[2][BB * HH];
__device__ float g_r0[BB * HH];
__device__ float g_z0[BB * HH];
__device__ float g_r1[BB * HH];
__device__ float g_z1[BB * HH];
__device__ unsigned g_barCnt;  // zero-init at load; self-resetting
__device__ unsigned g_barGen;  // monotonically increasing across launches (wrap-safe)

__device__ __forceinline__ float4 ld4(const float* p) {
    return *reinterpret_cast<const float4*>(p);
}

// Software grid barrier: all NCTA CTAs are co-resident (1 CTA/SM, 148 <= #SMs).
__device__ __forceinline__ void gridBarrier() {
    __syncthreads();
    if (threadIdx.x == 0) {
        __threadfence();
        volatile unsigned* vg = &g_barGen;
        unsigned gen = *vg;
        unsigned old = atomicAdd(&g_barCnt, 1u);
        if (old == NCTA - 1) {
            g_barCnt = 0u;
            __threadfence();
            atomicAdd(&g_barGen, 1u);
        } else {
            while (*vg == gen) { }
        }
        __threadfence();
    }
    __syncthreads();
}

// Stage one [64 x KC] chunk of the activation matrix A into smem.
// PH1: A = [x_t, h0]        (K=1536)
// PH2: A = [x_t, h0*r0]     (K=1536)
// PH3: A = [h0', h1]        (K=2048)
// PH4: A = [h0', h1*r1]     (K=2048)
template <int PH>
__device__ __forceinline__ void stageChunk(float* sA, int k0, int t,
        const float* __restrict__ x, const float* __restrict__ h0c,
        const float* __restrict__ h0n, const float* __restrict__ h1c)
{
    #pragma unroll
    for (int i = threadIdx.x * 4; i < BB * KC; i += NTHR * 4) {
        int m  = i >> 7;     // row (one row per warp-iteration: perfectly coalesced)
        int kk = i & 127;
        int k  = k0 + kk;
        float4 v;
        if (PH <= 2) {
            if (k < II) {
                v = ld4(x + (size_t)m * (SS * II) + t * II + k);
            } else {
                int o = m * HH + (k - II);
                v = ld4(h0c + o);
                if (PH == 2) {
                    float4 r = ld4(g_r0 + o);
                    v.x *= r.x; v.y *= r.y; v.z *= r.z; v.w *= r.w;
                }
            }
        } else {
            if (k < HH) {
                v = ld4(h0n + m * HH + k);
            } else {
                int o = m * HH + (k - HH);
                v = ld4(h1c + o);
                if (PH == 4) {
                    float4 r = ld4(g_r1 + o);
                    v.x *= r.x; v.y *= r.y; v.z *= r.z; v.w *= r.w;
                }
            }
        }
        *reinterpret_cast<float4*>(sA + m * KC + kk) = v;
    }
}

// One GEMM phase: out[64, N] = A[64, K] @ W[N, K]^T  (+ bias, activation, state update)
// Each warp owns a PAIR of adjacent output columns; K split across 8 lane-groups.
template <int PH>
__device__ void runPhase(float* sA, int t, int par,
    const float* __restrict__ x,
    const float* __restrict__ Wr0, const float* __restrict__ br0,
    const float* __restrict__ Wz0, const float* __restrict__ bz0,
    const float* __restrict__ Wc0, const float* __restrict__ bc0,
    const float* __restrict__ Wr1, const float* __restrict__ br1,
    const float* __restrict__ Wz1, const float* __restrict__ bz1,
    const float* __restrict__ Wc1, const float* __restrict__ bc1)
{
    const int K     = (PH <= 2) ? KK0 : KK1;
    const int NPAIR = (PH == 1 || PH == 3) ? HH : (HH / 2);  // column pairs
    const float* h0c = g_h0[par];
    float*       h0n = g_h0[par ^ 1];
    const float* h1c = g_h1[par];
    float*       h1n = g_h1[par ^ 1];

    const int wid  = threadIdx.x >> 5;
    const int lane = threadIdx.x & 31;
    const int kg   = lane & 7;   // K-group (8 lanes cover 128B contiguous -> conflict-free)
    const int mg   = lane >> 3;  // M-group (4 groups of 16 rows)

    // warp-major mapping keeps every SMSP busy even in half-size phases
    const int p      = wid * NCTA + blockIdx.x;
    const bool active = (p < NPAIR);
    const int n0 = 2 * p;

    const float* w0 = nullptr;
    const float* w1 = nullptr;
    const float* bias = nullptr;
    int nb = 0;
    if (active) {
        if (PH == 1) {
            if (n0 < HH) { w0 = Wr0 + (size_t)n0 * KK0;        bias = br0; nb = n0; }
            else         { w0 = Wz0 + (size_t)(n0 - HH) * KK0; bias = bz0; nb = n0 - HH; }
        } else if (PH == 2) {
            w0 = Wc0 + (size_t)n0 * KK0; bias = bc0; nb = n0;
        } else if (PH == 3) {
            if (n0 < HH) { w0 = Wr1 + (size_t)n0 * KK1;        bias = br1; nb = n0; }
            else         { w0 = Wz1 + (size_t)(n0 - HH) * KK1; bias = bz1; nb = n0 - HH; }
        } else {
            w0 = Wc1 + (size_t)n0 * KK1; bias = bc1; nb = n0;
        }
        w1 = w0 + K;  // adjacent column, same gate (gate boundary is even)
    }

    float acc0[16], acc1[16];
    #pragma unroll
    for (int i = 0; i < 16; i++) { acc0[i] = 0.f; acc1[i] = 0.f; }

    for (int kc = 0; kc < K; kc += KC) {
        __syncthreads();
        stageChunk<PH>(sA, kc, t, x, h0c, h0n, h1c);
        __syncthreads();
        if (active) {
            #pragma unroll
            for (int j = 0; j < 4; j++) {
                const int ko = j * 32 + kg * 4;
                float4 wv0 = ld4(w0 + kc + ko);
                float4 wv1 = ld4(w1 + kc + ko);
                #pragma unroll
                for (int mi = 0; mi < 16; mi++) {
                    float4 av = ld4(sA + (mg * 16 + mi) * KC + ko);
                    acc0[mi] = fmaf(av.x, wv0.x, acc0[mi]);
                    acc0[mi] = fmaf(av.y, wv0.y, acc0[mi]);
                    acc0[mi] = fmaf(av.z, wv0.z, acc0[mi]);
                    acc0[mi] = fmaf(av.w, wv0.w, acc0[mi]);
                    acc1[mi] = fmaf(av.x, wv1.x, acc1[mi]);
                    acc1[mi] = fmaf(av.y, wv1.y, acc1[mi]);
                    acc1[mi] = fmaf(av.z, wv1.z, acc1[mi]);
                    acc1[mi] = fmaf(av.w, wv1.w, acc1[mi]);
                }
            }
        }
    }

    if (active) {
        #pragma unroll
        for (int mi = 0; mi < 16; mi++) {
            float v0 = acc0[mi], v1 = acc1[mi];
            #pragma unroll
            for (int d = 1; d < 8; d <<= 1) {
                v0 += __shfl_xor_sync(0xffffffffu, v0, d);
                v1 += __shfl_xor_sync(0xffffffffu, v1, d);
            }
            if (kg == 0) {
                const int m  = mg * 16 + mi;
                const float s0 = v0 + bias[nb];
                const float s1 = v1 + bias[nb + 1];
                if (PH == 1) {
                    float* dst = (n0 < HH) ? g_r0 : g_z0;
                    dst[m * HH + nb]     = 1.f / (1.f + expf(-s0));
                    dst[m * HH + nb + 1] = 1.f / (1.f + expf(-s1));
                } else if (PH == 3) {
                    float* dst = (n0 < HH) ? g_r1 : g_z1;
                    dst[m * HH + nb]     = 1.f / (1.f + expf(-s0));
                    dst[m * HH + nb + 1] = 1.f / (1.f + expf(-s1));
                } else if (PH == 2) {
                    const float c0v = tanhf(s0), c1v = tanhf(s1);
                    const int o0 = m * HH + n0, o1 = o0 + 1;
                    const float ha = h0c[o0], za = g_z0[o0];
                    const float hb = h0c[o1], zb = g_z0[o1];
                    h0n[o0] = ha * za + (1.f - za) * c0v;
                    h0n[o1] = hb * zb + (1.f - zb) * c1v;
                } else {  // PH == 4
                    const float c0v = tanhf(s0), c1v = tanhf(s1);
                    const int o0 = m * HH + n0, o1 = o0 + 1;
                    const float ha = h1c[o0], za = g_z1[o0];
                    const float hb = h1c[o1], zb = g_z1[o1];
                    h1n[o0] = ha * za + (1.f - za) * c0v;
                    h1n[o1] = hb * zb + (1.f - zb) * c1v;
                }
            }
        }
    }
}

__global__ void __launch_bounds__(NTHR, 1) rnn_persistent(
    const float* __restrict__ x,
    const float* __restrict__ Wr0, const float* __restrict__ br0,
    const float* __restrict__ Wz0, const float* __restrict__ bz0,
    const float* __restrict__ Wc0, const float* __restrict__ bc0,
    const float* __restrict__ Wr1, const float* __restrict__ br1,
    const float* __restrict__ Wz1, const float* __restrict__ bz1,
    const float* __restrict__ Wc1, const float* __restrict__ bc1,
    const float* __restrict__ Wreg, const float* __restrict__ breg,
    float* __restrict__ out)
{
    __shared__ __align__(16) float sA[BB * KC];

    // Device globals persist across launches -> must re-zero h every launch.
    for (int i = blockIdx.x * NTHR + threadIdx.x; i < BB * HH; i += NCTA * NTHR) {
        g_h0[0][i] = 0.f;
        g_h1[0][i] = 0.f;
    }
    gridBarrier();

    for (int t = 0; t < SS; t++) {
        const int par = t & 1;
        runPhase<1>(sA, t, par, x, Wr0, br0, Wz0, bz0, Wc0, bc0, Wr1, br1, Wz1, bz1, Wc1, bc1);
        gridBarrier();
        runPhase<2>(sA, t, par, x, Wr0, br0, Wz0, bz0, Wc0, bc0, Wr1, br1, Wz1, bz1, Wc1, bc1);
        gridBarrier();
        runPhase<3>(sA, t, par, x, Wr0, br0, Wz0, bz0, Wc0, bc0, Wr1, br1, Wz1, bz1, Wc1, bc1);
        gridBarrier();
        runPhase<4>(sA, t, par, x, Wr0, br0, Wz0, bz0, Wc0, bc0, Wr1, br1, Wz1, bz1, Wc1, bc1);
        gridBarrier();
    }

    // Final regressor: out[64,2] = h1_final @ Wreg^T + breg  (h1 final parity = 0)
    if (blockIdx.x == 0 && threadIdx.x < BB * 2) {
        const int m = threadIdx.x >> 1;
        const int o = threadIdx.x & 1;
        const float* h = g_h1[0] + m * HH;
        const float* w = Wreg + o * HH;
        float s = 0.f;
        #pragma unroll 8
        for (int k = 0; k < HH; k += 4) {
            float4 hv = ld4(h + k);
            float4 wv = ld4(w + k);
            s = fmaf(hv.x, wv.x, s);
            s = fmaf(hv.y, wv.y, s);
            s = fmaf(hv.z, wv.z, s);
            s = fmaf(hv.w, wv.w, s);
        }
        out[m * 2 + o] = s + breg[o];
    }
}

extern "C" void kernel_launch(void* const* d_in, const int* in_sizes, int n_in,
                              void* d_out, int out_size) {
    rnn_persistent<<<NCTA, NTHR>>>(
        (const float*)d_in[0],   // x
        (const float*)d_in[1],  (const float*)d_in[2],   // Wr0, br0
        (const float*)d_in[3],  (const float*)d_in[4],   // Wz0, bz0
        (const float*)d_in[5],  (const float*)d_in[6],   // Wc0, bc0
        (const float*)d_in[7],  (const float*)d_in[8],   // Wr1, br1
        (const float*)d_in[9],  (const float*)d_in[10],  // Wz1, bz1
        (const float*)d_in[11], (const float*)d_in[12],  // Wc1, bc1
        (const float*)d_in[13], (const float*)d_in[14],  // Wreg, breg
        (float*)d_out);
}

// round 3
// speedup vs baseline: 1.0432x; 1.0432x over previous
#include <cuda_runtime.h>
#include <math.h>

#define BB 64
#define SS 512
#define II 512
#define HH 1024
#define KK0 1536
#define KK1 2048
#define NCTA 148
#define NTHR 256
#define KC 128

// Persistent device state (allowed: __device__ globals, no allocation)
__device__ float g_h0[2][BB * HH];
__device__ float g_h1[2][BB * HH];
__device__ float g_r0[BB * HH];
__device__ float g_z0[BB * HH];
__device__ float g_r1[BB * HH];
__device__ float g_z1[BB * HH];
__device__ unsigned g_barCnt;  // zero-init at load; self-resetting
__device__ unsigned g_barGen;  // monotonically increasing across launches (wrap-safe)

__device__ __forceinline__ float4 ld4(const float* p) {
    return *reinterpret_cast<const float4*>(p);
}

// Software grid barrier: all NCTA CTAs are co-resident (1 CTA/SM, 148 <= #SMs).
__device__ __forceinline__ void gridBarrier() {
    __syncthreads();
    if (threadIdx.x == 0) {
        __threadfence();
        volatile unsigned* vg = &g_barGen;
        unsigned gen = *vg;
        unsigned old = atomicAdd(&g_barCnt, 1u);
        if (old == NCTA - 1) {
            g_barCnt = 0u;
            __threadfence();
            atomicAdd(&g_barGen, 1u);
        } else {
            while (*vg == gen) { }
        }
        __threadfence();
    }
    __syncthreads();
}

// Stage one [64 x KC] chunk of the activation matrix A into smem.
// PH1: A = [x_t, h0]        (K=1536)
// PH2: A = [x_t, h0*r0]     (K=1536)
// PH3: A = [h0', h1]        (K=2048)
// PH4: A = [h0', h1*r1]     (K=2048)
template <int PH>
__device__ __forceinline__ void stageChunk(float* sA, int k0, int t,
        const float* __restrict__ x, const float* __restrict__ h0c,
        const float* __restrict__ h0n, const float* __restrict__ h1c)
{
    #pragma unroll
    for (int i = threadIdx.x * 4; i < BB * KC; i += NTHR * 4) {
        int m  = i >> 7;     // row (one row per warp-iteration: perfectly coalesced)
        int kk = i & 127;
        int k  = k0 + kk;
        float4 v;
        if (PH <= 2) {
            if (k < II) {
                v = ld4(x + (size_t)m * (SS * II) + t * II + k);
            } else {
                int o = m * HH + (k - II);
                v = ld4(h0c + o);
                if (PH == 2) {
                    float4 r = ld4(g_r0 + o);
                    v.x *= r.x; v.y *= r.y; v.z *= r.z; v.w *= r.w;
                }
            }
        } else {
            if (k < HH) {
                v = ld4(h0n + m * HH + k);
            } else {
                int o = m * HH + (k - HH);
                v = ld4(h1c + o);
                if (PH == 4) {
                    float4 r = ld4(g_r1 + o);
                    v.x *= r.x; v.y *= r.y; v.z *= r.z; v.w *= r.w;
                }
            }
        }
        *reinterpret_cast<float4*>(sA + m * KC + kk) = v;
    }
}

// One GEMM phase: out[64, N] = A[64, K] @ W[N, K]^T  (+ bias, activation, state update)
// Each warp owns a PAIR of adjacent output columns; K split across 8 lane-groups.
template <int PH>
__device__ void runPhase(float* sA, int t, int par,
    const float* __restrict__ x,
    const float* __restrict__ Wr0, const float* __restrict__ br0,
    const float* __restrict__ Wz0, const float* __restrict__ bz0,
    const float* __restrict__ Wc0, const float* __restrict__ bc0,
    const float* __restrict__ Wr1, const float* __restrict__ br1,
    const float* __restrict__ Wz1, const float* __restrict__ bz1,
    const float* __restrict__ Wc1, const float* __restrict__ bc1)
{
    const int K     = (PH <= 2) ? KK0 : KK1;
    const int NPAIR = (PH == 1 || PH == 3) ? HH : (HH / 2);  // column pairs
    const float* h0c = g_h0[par];
    float*       h0n = g_h0[par ^ 1];
    const float* h1c = g_h1[par];
    float*       h1n = g_h1[par ^ 1];

    const int wid  = threadIdx.x >> 5;
    const int lane = threadIdx.x & 31;
    const int kg   = lane & 7;   // K-group (8 lanes cover 128B contiguous -> conflict-free)
    const int mg   = lane >> 3;  // M-group (4 groups of 16 rows)

    // warp-major mapping keeps every SMSP busy even in half-size phases
    const int p      = wid * NCTA + blockIdx.x;
    const bool active = (p < NPAIR);
    const int n0 = 2 * p;

    const float* w0 = nullptr;
    const float* w1 = nullptr;
    const float* bias = nullptr;
    int nb = 0;
    if (active) {
        if (PH == 1) {
            if (n0 < HH) { w0 = Wr0 + (size_t)n0 * KK0;        bias = br0; nb = n0; }
            else         { w0 = Wz0 + (size_t)(n0 - HH) * KK0; bias = bz0; nb = n0 - HH; }
        } else if (PH == 2) {
            w0 = Wc0 + (size_t)n0 * KK0; bias = bc0; nb = n0;
        } else if (PH == 3) {
            if (n0 < HH) { w0 = Wr1 + (size_t)n0 * KK1;        bias = br1; nb = n0; }
            else         { w0 = Wz1 + (size_t)(n0 - HH) * KK1; bias = bz1; nb = n0 - HH; }
        } else {
            w0 = Wc1 + (size_t)n0 * KK1; bias = bc1; nb = n0;
        }
        w1 = w0 + K;  // adjacent column, same gate (gate boundary is even)
    }

    float acc0[16], acc1[16];
    #pragma unroll
    for (int i = 0; i < 16; i++) { acc0[i] = 0.f; acc1[i] = 0.f; }

    for (int kc = 0; kc < K; kc += KC) {
        __syncthreads();
        stageChunk<PH>(sA, kc, t, x, h0c, h0n, h1c);
        __syncthreads();
        if (active) {
            #pragma unroll
            for (int j = 0; j < 4; j++) {
                const int ko = j * 32 + kg * 4;
                float4 wv0 = ld4(w0 + kc + ko);
                float4 wv1 = ld4(w1 + kc + ko);
                #pragma unroll
                for (int mi = 0; mi < 16; mi++) {
                    float4 av = ld4(sA + (mg * 16 + mi) * KC + ko);
                    acc0[mi] = fmaf(av.x, wv0.x, acc0[mi]);
                    acc0[mi] = fmaf(av.y, wv0.y, acc0[mi]);
                    acc0[mi] = fmaf(av.z, wv0.z, acc0[mi]);
                    acc0[mi] = fmaf(av.w, wv0.w, acc0[mi]);
                    acc1[mi] = fmaf(av.x, wv1.x, acc1[mi]);
                    acc1[mi] = fmaf(av.y, wv1.y, acc1[mi]);
                    acc1[mi] = fmaf(av.z, wv1.z, acc1[mi]);
                    acc1[mi] = fmaf(av.w, wv1.w, acc1[mi]);
                }
            }
        }
    }

    if (active) {
        #pragma unroll
        for (int mi = 0; mi < 16; mi++) {
            float v0 = acc0[mi], v1 = acc1[mi];
            #pragma unroll
            for (int d = 1; d < 8; d <<= 1) {
                v0 += __shfl_xor_sync(0xffffffffu, v0, d);
                v1 += __shfl_xor_sync(0xffffffffu, v1, d);
            }
            if (kg == 0) {
                const int m  = mg * 16 + mi;
                const float s0 = v0 + bias[nb];
                const float s1 = v1 + bias[nb + 1];
                if (PH == 1) {
                    float* dst = (n0 < HH) ? g_r0 : g_z0;
                    dst[m * HH + nb]     = 1.f / (1.f + expf(-s0));
                    dst[m * HH + nb + 1] = 1.f / (1.f + expf(-s1));
                } else if (PH == 3) {
                    float* dst = (n0 < HH) ? g_r1 : g_z1;
                    dst[m * HH + nb]     = 1.f / (1.f + expf(-s0));
                    dst[m * HH + nb + 1] = 1.f / (1.f + expf(-s1));
                } else if (PH == 2) {
                    const float c0v = tanhf(s0), c1v = tanhf(s1);
                    const int o0 = m * HH + n0, o1 = o0 + 1;
                    const float ha = h0c[o0], za = g_z0[o0];
                    const float hb = h0c[o1], zb = g_z0[o1];
                    h0n[o0] = ha * za + (1.f - za) * c0v;
                    h0n[o1] = hb * zb + (1.f - zb) * c1v;
                } else {  // PH == 4
                    const float c0v = tanhf(s0), c1v = tanhf(s1);
                    const int o0 = m * HH + n0, o1 = o0 + 1;
                    const float ha = h1c[o0], za = g_z1[o0];
                    const float hb = h1c[o1], zb = g_z1[o1];
                    h1n[o0] = ha * za + (1.f - za) * c0v;
                    h1n[o1] = hb * zb + (1.f - zb) * c1v;
                }
            }
        }
    }
}

__global__ void __launch_bounds__(NTHR, 1) rnn_persistent(
    const float* __restrict__ x,
    const float* __restrict__ Wr0, const float* __restrict__ br0,
    const float* __restrict__ Wz0, const float* __restrict__ bz0,
    const float* __restrict__ Wc0, const float* __restrict__ bc0,
    const float* __restrict__ Wr1, const float* __restrict__ br1,
    const float* __restrict__ Wz1, const float* __restrict__ bz1,
    const float* __restrict__ Wc1, const float* __restrict__ bc1,
    const float* __restrict__ Wreg, const float* __restrict__ breg,
    float* __restrict__ out)
{
    __shared__ __align__(16) float sA[BB * KC];

    // Device globals persist across launches -> must re-zero h every launch.
    for (int i = blockIdx.x * NTHR + threadIdx.x; i < BB * HH; i += NCTA * NTHR) {
        g_h0[0][i] = 0.f;
        g_h1[0][i] = 0.f;
    }
    gridBarrier();

    for (int t = 0; t < SS; t++) {
        const int par = t & 1;
        runPhase<1>(sA, t, par, x, Wr0, br0, Wz0, bz0, Wc0, bc0, Wr1, br1, Wz1, bz1, Wc1, bc1);
        gridBarrier();
        runPhase<2>(sA, t, par, x, Wr0, br0, Wz0, bz0, Wc0, bc0, Wr1, br1, Wz1, bz1, Wc1, bc1);
        gridBarrier();
        runPhase<3>(sA, t, par, x, Wr0, br0, Wz0, bz0, Wc0, bc0, Wr1, br1, Wz1, bz1, Wc1, bc1);
        gridBarrier();
        runPhase<4>(sA, t, par, x, Wr0, br0, Wz0, bz0, Wc0, bc0, Wr1, br1, Wz1, bz1, Wc1, bc1);
        gridBarrier();
    }

    // Final regressor: out[64,2] = h1_final @ Wreg^T + breg  (h1 final parity = 0)
    if (blockIdx.x == 0 && threadIdx.x < BB * 2) {
        const int m = threadIdx.x >> 1;
        const int o = threadIdx.x & 1;
        const float* h = g_h1[0] + m * HH;
        const float* w = Wreg + o * HH;
        float s = 0.f;
        #pragma unroll 8
        for (int k = 0; k < HH; k += 4) {
            float4 hv = ld4(h + k);
            float4 wv = ld4(w + k);
            s = fmaf(hv.x, wv.x, s);
            s = fmaf(hv.y, wv.y, s);
            s = fmaf(hv.z, wv.z, s);
            s = fmaf(hv.w, wv.w, s);
        }
        out[m * 2 + o] = s + breg[o];
    }
}

extern "C" void kernel_launch(void* const* d_in, const int* in_sizes, int n_in,
                              void* d_out, int out_size) {
    rnn_persistent<<<NCTA, NTHR>>>(
        (const float*)d_in[0],   // x
        (const float*)d_in[1],  (const float*)d_in[2],   // Wr0, br0
        (const float*)d_in[3],  (const float*)d_in[4],   // Wz0, bz0
        (const float*)d_in[5],  (const float*)d_in[6],   // Wc0, bc0
        (const float*)d_in[7],  (const float*)d_in[8],   // Wr1, br1
        (const float*)d_in[9],  (const float*)d_in[10],  // Wz1, bz1
        (const float*)d_in[11], (const float*)d_in[12],  // Wc1, bc1
        (const float*)d_in[13], (const float*)d_in[14],  // Wreg, breg
        (float*)d_out);
}

// round 4
// speedup vs baseline: 1.5405x; 1.4767x over previous
#include <cuda_runtime.h>
#include <math.h>

#define BB 64
#define SS 512
#define II 512
#define HH 1024
#define KK0 1536
#define KK1 2048
#define NCTA 148
#define NTHR 256
#define KC 128
#define CHUNK_F (BB * KC)   // 8192 floats per chunk buffer

// Dynamic smem layout (floats):
//  [0,16384)      sA: double-buffered chunk (PH1/3; half-0 stream in PH2/4)
//  [16384,32768)  sB: double-buffered chunk (half-1 stream in PH2/4)
//  [32768,33280)  sPart: 4 pair-slots x 64 rows x 2 cols partials
#define SMEM_FLOATS (32768 + 512)

// Persistent device state
__device__ float g_h0[2][BB * HH];
__device__ float g_h1[2][BB * HH];
__device__ float g_r0[BB * HH];
__device__ float g_z0[BB * HH];
__device__ float g_r1[BB * HH];
__device__ float g_z1[BB * HH];
__device__ unsigned g_barCnt;
__device__ unsigned g_barGen;

__device__ __forceinline__ float4 ld4(const float* p) {
    return *reinterpret_cast<const float4*>(p);
}

// Software grid barrier: all NCTA CTAs co-resident (1 CTA/SM).
__device__ __forceinline__ void gridBarrier() {
    __syncthreads();
    if (threadIdx.x == 0) {
        __threadfence();
        volatile unsigned* vg = &g_barGen;
        unsigned gen = *vg;
        unsigned old = atomicAdd(&g_barCnt, 1u);
        if (old == NCTA - 1) {
            g_barCnt = 0u;
            __threadfence();
            atomicAdd(&g_barGen, 1u);
        } else {
            while (*vg == gen) { __nanosleep(64); }
        }
        __threadfence();
    }
    __syncthreads();
}

// Load one [64 x KC] chunk of the activation matrix A into registers.
// PH1: A = [x_t, h0]     PH2: A = [x_t, h0*r0]
// PH3: A = [h0', h1]     PH4: A = [h0', h1*r1]
template <int PH>
__device__ __forceinline__ void loadStage(float4* v, int k0, int t,
        const float* __restrict__ x, const float* __restrict__ h0c,
        const float* __restrict__ h0n, const float* __restrict__ h1c)
{
    #pragma unroll
    for (int it = 0; it < 8; it++) {
        int idx = it * 1024 + threadIdx.x * 4;
        int m = idx >> 7, kk = idx & 127, k = k0 + kk;
        float4 w;
        if (PH <= 2) {
            if (k < II) {
                w = ld4(x + (size_t)m * (SS * II) + t * II + k);
            } else {
                int o = m * HH + (k - II);
                w = ld4(h0c + o);
                if (PH == 2) {
                    float4 r = ld4(g_r0 + o);
                    w.x *= r.x; w.y *= r.y; w.z *= r.z; w.w *= r.w;
                }
            }
        } else {
            if (k < HH) {
                w = ld4(h0n + m * HH + k);
            } else {
                int o = m * HH + (k - HH);
                w = ld4(h1c + o);
                if (PH == 4) {
                    float4 r = ld4(g_r1 + o);
                    w.x *= r.x; w.y *= r.y; w.z *= r.z; w.w *= r.w;
                }
            }
        }
        v[it] = w;
    }
}

__device__ __forceinline__ void storeStage(float* s, const float4* v) {
    #pragma unroll
    for (int it = 0; it < 8; it++)
        *reinterpret_cast<float4*>(s + it * 1024 + threadIdx.x * 4) = v[it];
}

// 16 rows x 2 cols x 4 K-values of FMA from one staged chunk.
__device__ __forceinline__ void fmaBlock(const float* __restrict__ s, int ko, int mg,
        float4 wa, float4 wb, float* acc0, float* acc1)
{
    #pragma unroll
    for (int mi = 0; mi < 16; mi++) {
        float4 av = ld4(s + (mg * 16 + mi) * KC + ko);
        acc0[mi] = fmaf(av.x, wa.x, acc0[mi]);
        acc0[mi] = fmaf(av.y, wa.y, acc0[mi]);
        acc0[mi] = fmaf(av.z, wa.z, acc0[mi]);
        acc0[mi] = fmaf(av.w, wa.w, acc0[mi]);
        acc1[mi] = fmaf(av.x, wb.x, acc1[mi]);
        acc1[mi] = fmaf(av.y, wb.y, acc1[mi]);
        acc1[mi] = fmaf(av.z, wb.z, acc1[mi]);
        acc1[mi] = fmaf(av.w, wb.w, acc1[mi]);
    }
}

// PH1/PH3: r & z gates. 1024 column-pairs, one pair per warp, K split 8-way per lane.
// Double-buffered staging + weight prefetch across j/chunks.
template <int PH>
__device__ void runPhaseRZ(float* sA, int t, int par,
    const float* __restrict__ x,
    const float* __restrict__ Wr, const float* __restrict__ br,
    const float* __restrict__ Wz, const float* __restrict__ bz)
{
    const int K = (PH == 1) ? KK0 : KK1;
    const int nc = K / KC;
    const float* h0c = g_h0[par];
    const float* h0n = g_h0[par ^ 1];
    const float* h1c = g_h1[par];

    const int wid = threadIdx.x >> 5, lane = threadIdx.x & 31;
    const int kg = lane & 7, mg = lane >> 3;
    const int p = wid * NCTA + blockIdx.x;
    const bool active = (p < HH);
    const int n0 = 2 * p;

    const float* w0 = nullptr; const float* w1 = nullptr;
    const float* bias = nullptr; int nb = 0;
    if (active) {
        if (n0 < HH) { w0 = Wr + (size_t)n0 * K;        bias = br; nb = n0; }
        else         { w0 = Wz + (size_t)(n0 - HH) * K; bias = bz; nb = n0 - HH; }
        w1 = w0 + K;
    }

    float4 stg[8];
    loadStage<PH>(stg, 0, t, x, h0c, h0n, h1c);
    storeStage(sA, stg);
    __syncthreads();

    float4 wa = make_float4(0.f,0.f,0.f,0.f), wb = wa;
    if (active) { wa = ld4(w0 + kg * 4); wb = ld4(w1 + kg * 4); }

    float acc0[16], acc1[16];
    #pragma unroll
    for (int i = 0; i < 16; i++) { acc0[i] = 0.f; acc1[i] = 0.f; }

    for (int c = 0; c < nc; c++) {
        const bool more = (c + 1 < nc);
        if (more) loadStage<PH>(stg, (c + 1) * KC, t, x, h0c, h0n, h1c);
        const float* s = sA + (c & 1) * CHUNK_F;
        #pragma unroll
        for (int j = 0; j < 4; j++) {
            int nk = (j < 3) ? (c * KC + (j + 1) * 32 + kg * 4)
                             : (more ? ((c + 1) * KC + kg * 4) : kg * 4);
            float4 na = wa, nb4 = wb;
            if (active) { na = ld4(w0 + nk); nb4 = ld4(w1 + nk); }
            if (active) fmaBlock(s, j * 32 + kg * 4, mg, wa, wb, acc0, acc1);
            wa = na; wb = nb4;
        }
        if (more) storeStage(sA + ((c + 1) & 1) * CHUNK_F, stg);
        __syncthreads();
    }

    if (active) {
        float* dst = (n0 < HH) ? ((PH == 1) ? g_r0 : g_r1)
                               : ((PH == 1) ? g_z0 : g_z1);
        #pragma unroll
        for (int mi = 0; mi < 16; mi++) {
            float v0 = acc0[mi], v1 = acc1[mi];
            #pragma unroll
            for (int d = 1; d < 8; d <<= 1) {
                v0 += __shfl_xor_sync(0xffffffffu, v0, d);
                v1 += __shfl_xor_sync(0xffffffffu, v1, d);
            }
            if (kg == 0) {
                const int m = mg * 16 + mi;
                dst[m * HH + nb]     = 1.f / (1.f + expf(-(v0 + bias[nb])));
                dst[m * HH + nb + 1] = 1.f / (1.f + expf(-(v1 + bias[nb + 1])));
            }
        }
    }
}

// PH2/PH4: candidate gate + h update. 512 pairs; each pair computed by TWO warps
// of the same CTA (warp pair 2s, 2s+1), each owning half of K. Two chunk streams
// (sA for half 0, sB for half 1) staged simultaneously; partials combined in smem.
template <int PH>
__device__ void runPhaseC(float* sA, float* sB, float* sPart, int t, int par,
    const float* __restrict__ x,
    const float* __restrict__ Wc, const float* __restrict__ bc)
{
    const int K = (PH == 2) ? KK0 : KK1;
    const int nch = K / (2 * KC);   // chunks per half: 6 or 8
    const float* h0c = g_h0[par];
    float*       h0n = g_h0[par ^ 1];
    const float* h1c = g_h1[par];
    float*       h1n = g_h1[par ^ 1];

    const int wid = threadIdx.x >> 5, lane = threadIdx.x & 31;
    const int kg = lane & 7, mg = lane >> 3;
    const int slot = wid >> 1;          // 0..3 CTA-local pair slot
    const int half = wid & 1;           // K-half owned by this warp
    const int p = slot * NCTA + blockIdx.x;
    const bool active = (p < HH / 2);   // 512 pairs
    const int n0 = 2 * p;

    const float* w0 = nullptr; const float* w1 = nullptr;
    if (active) { w0 = Wc + (size_t)n0 * K; w1 = w0 + K; }
    const int kbase = half * (K / 2);

    float4 stgA[8], stgB[8];
    loadStage<PH>(stgA, 0,     t, x, h0c, h0n, h1c);
    loadStage<PH>(stgB, K / 2, t, x, h0c, h0n, h1c);
    storeStage(sA, stgA);
    storeStage(sB, stgB);
    __syncthreads();

    float4 wa = make_float4(0.f,0.f,0.f,0.f), wb = wa;
    if (active) { wa = ld4(w0 + kbase + kg * 4); wb = ld4(w1 + kbase + kg * 4); }

    float acc0[16], acc1[16];
    #pragma unroll
    for (int i = 0; i < 16; i++) { acc0[i] = 0.f; acc1[i] = 0.f; }

    float* myBuf = half ? sB : sA;

    for (int c = 0; c < nch; c++) {
        const bool more = (c + 1 < nch);
        if (more) {
            loadStage<PH>(stgA, (c + 1) * KC,         t, x, h0c, h0n, h1c);
            loadStage<PH>(stgB, K / 2 + (c + 1) * KC, t, x, h0c, h0n, h1c);
        }
        const float* s = myBuf + (c & 1) * CHUNK_F;
        #pragma unroll
        for (int j = 0; j < 4; j++) {
            int nk = kbase + ((j < 3) ? (c * KC + (j + 1) * 32 + kg * 4)
                                      : (more ? ((c + 1) * KC + kg * 4) : kg * 4));
            float4 na = wa, nb4 = wb;
            if (active) { na = ld4(w0 + nk); nb4 = ld4(w1 + nk); }
            if (active) fmaBlock(s, j * 32 + kg * 4, mg, wa, wb, acc0, acc1);
            wa = na; wb = nb4;
        }
        if (more) {
            storeStage(sA + ((c + 1) & 1) * CHUNK_F, stgA);
            storeStage(sB + ((c + 1) & 1) * CHUNK_F, stgB);
        }
        __syncthreads();
    }

    // warp-level K reduce (8 lanes per K-group)
    #pragma unroll
    for (int mi = 0; mi < 16; mi++) {
        float v0 = acc0[mi], v1 = acc1[mi];
        #pragma unroll
        for (int d = 1; d < 8; d <<= 1) {
            v0 += __shfl_xor_sync(0xffffffffu, v0, d);
            v1 += __shfl_xor_sync(0xffffffffu, v1, d);
        }
        acc0[mi] = v0; acc1[mi] = v1;
    }

    // half 0 publishes partials
    if (active && half == 0 && kg == 0) {
        #pragma unroll
        for (int mi = 0; mi < 16; mi++) {
            const int m = mg * 16 + mi;
            sPart[slot * 128 + m * 2 + 0] = acc0[mi];
            sPart[slot * 128 + m * 2 + 1] = acc1[mi];
        }
    }
    __syncthreads();

    // half 1 combines, activates, updates h
    if (active && half == 1 && kg == 0) {
        #pragma unroll
        for (int mi = 0; mi < 16; mi++) {
            const int m = mg * 16 + mi;
            const float s0 = acc0[mi] + sPart[slot * 128 + m * 2 + 0] + bc[n0];
            const float s1 = acc1[mi] + sPart[slot * 128 + m * 2 + 1] + bc[n0 + 1];
            const float c0v = tanhf(s0), c1v = tanhf(s1);
            const int o0 = m * HH + n0, o1 = o0 + 1;
            if (PH == 2) {
                const float ha = h0c[o0], za = g_z0[o0];
                const float hb = h0c[o1], zb = g_z0[o1];
                h0n[o0] = ha * za + (1.f - za) * c0v;
                h0n[o1] = hb * zb + (1.f - zb) * c1v;
            } else {
                const float ha = h1c[o0], za = g_z1[o0];
                const float hb = h1c[o1], zb = g_z1[o1];
                h1n[o0] = ha * za + (1.f - za) * c0v;
                h1n[o1] = hb * zb + (1.f - zb) * c1v;
            }
        }
    }
}

__global__ void __launch_bounds__(NTHR, 1) rnn_persistent(
    const float* __restrict__ x,
    const float* __restrict__ Wr0, const float* __restrict__ br0,
    const float* __restrict__ Wz0, const float* __restrict__ bz0,
    const float* __restrict__ Wc0, const float* __restrict__ bc0,
    const float* __restrict__ Wr1, const float* __restrict__ br1,
    const float* __restrict__ Wz1, const float* __restrict__ bz1,
    const float* __restrict__ Wc1, const float* __restrict__ bc1,
    const float* __restrict__ Wreg, const float* __restrict__ breg,
    float* __restrict__ out)
{
    extern __shared__ float smem[];
    float* sA    = smem;
    float* sB    = smem + 16384;
    float* sPart = smem + 32768;

    // re-zero persistent h every launch
    for (int i = blockIdx.x * NTHR + threadIdx.x; i < BB * HH; i += NCTA * NTHR) {
        g_h0[0][i] = 0.f;
        g_h1[0][i] = 0.f;
    }
    gridBarrier();

    for (int t = 0; t < SS; t++) {
        const int par = t & 1;
        runPhaseRZ<1>(sA, t, par, x, Wr0, br0, Wz0, bz0);
        gridBarrier();
        runPhaseC<2>(sA, sB, sPart, t, par, x, Wc0, bc0);
        gridBarrier();
        runPhaseRZ<3>(sA, t, par, x, Wr1, br1, Wz1, bz1);
        gridBarrier();
        runPhaseC<4>(sA, sB, sPart, t, par, x, Wc1, bc1);
        gridBarrier();
    }

    // Final regressor: out[64,2] = h1_final @ Wreg^T + breg (final parity -> g_h1[0])
    if (blockIdx.x == 0 && threadIdx.x < BB * 2) {
        const int m = threadIdx.x >> 1;
        const int o = threadIdx.x & 1;
        const float* h = g_h1[0] + m * HH;
        const float* w = Wreg + o * HH;
        float s = 0.f;
        #pragma unroll 8
        for (int k = 0; k < HH; k += 4) {
            float4 hv = ld4(h + k);
            float4 wv = ld4(w + k);
            s = fmaf(hv.x, wv.x, s);
            s = fmaf(hv.y, wv.y, s);
            s = fmaf(hv.z, wv.z, s);
            s = fmaf(hv.w, wv.w, s);
        }
        out[m * 2 + o] = s + breg[o];
    }
}

extern "C" void kernel_launch(void* const* d_in, const int* in_sizes, int n_in,
                              void* d_out, int out_size) {
    static_assert(SMEM_FLOATS * sizeof(float) == 133120, "smem layout");
    cudaFuncSetAttribute(rnn_persistent,
                         cudaFuncAttributeMaxDynamicSharedMemorySize,
                         SMEM_FLOATS * sizeof(float));
    rnn_persistent<<<NCTA, NTHR, SMEM_FLOATS * sizeof(float)>>>(
        (const float*)d_in[0],
        (const float*)d_in[1],  (const float*)d_in[2],
        (const float*)d_in[3],  (const float*)d_in[4],
        (const float*)d_in[5],  (const float*)d_in[6],
        (const float*)d_in[7],  (const float*)d_in[8],
        (const float*)d_in[9],  (const float*)d_in[10],
        (const float*)d_in[11], (const float*)d_in[12],
        (const float*)d_in[13], (const float*)d_in[14],
        (float*)d_out);
}